// round 12
// baseline (speedup 1.0000x reference)
#include <cuda_runtime.h>
#include <cuda_fp16.h>

#define D 128
#define NMAX 100000
#define BKP 72   // padded row stride in halves: banks (36r + c/2) mod 32 conflict-free

__device__ __half g_h[2][(size_t)NMAX * D];
__device__ int g_idx64;

__device__ __forceinline__ void mma_f16(float c[4], unsigned a0, unsigned a1,
                                        unsigned a2, unsigned a3,
                                        unsigned b0, unsigned b1) {
    asm volatile(
        "mma.sync.aligned.m16n8k16.row.col.f32.f16.f16.f32 "
        "{%0,%1,%2,%3},{%4,%5,%6,%7},{%8,%9},{%0,%1,%2,%3};"
        : "+f"(c[0]), "+f"(c[1]), "+f"(c[2]), "+f"(c[3])
        : "r"(a0), "r"(a1), "r"(a2), "r"(a3), "r"(b0), "r"(b1));
}

__device__ __forceinline__ uint2 ldg_el(const void* p, unsigned long long pol) {
    uint2 r;
    asm volatile("ld.global.nc.L2::cache_hint.v2.u32 {%0,%1}, [%2], %3;"
                 : "=r"(r.x), "=r"(r.y) : "l"(p), "l"(pol));
    return r;
}

__device__ __forceinline__ void stg_ef(void* p, float4 v, unsigned long long pol) {
    asm volatile("st.global.L2::cache_hint.v4.f32 [%0], {%1,%2,%3,%4}, %5;"
                 :: "l"(p), "f"(v.x), "f"(v.y), "f"(v.z), "f"(v.w), "l"(pol)
                 : "memory");
}

__device__ __forceinline__ unsigned h2u(__half2 h) {
    return *(unsigned*)&h;
}

// ---------------------------------------------------------------------------
// Node GEMM, fp16 mma.m16n8k16 (same 11-bit mantissa as tf32, 2x K/instr,
// half the LDS + MMA counts). One half (src/dst) per block via blockIdx.y.
// 256 threads, 8 warps 2x4, warp tile 64x32, BK=64 (2 iterations).
// ---------------------------------------------------------------------------
__global__ __launch_bounds__(256, 2) void node_gemm_half(
    const float* __restrict__ x,
    const float* __restrict__ Wsrc, const float* __restrict__ bsrc,
    const float* __restrict__ Wdst, const float* __restrict__ bdst,
    const long long* __restrict__ idxprobe, int N)
{
    __shared__ __half As[128][BKP];
    __shared__ __half Bs[128][BKP];

    const int tid  = threadIdx.x;
    const int half = blockIdx.y;

    if (blockIdx.x == 0 && half == 0 && tid == 0) {
        int ok = 0;
#pragma unroll
        for (int i = 0; i < 16; i++) {
            long long v = idxprobe[i];
            if (v >= 0 && v < (long long)N) ok++;
        }
        g_idx64 = (ok >= 12) ? 1 : 0;
    }

    const float* __restrict__ W  = half ? Wdst : Wsrc;
    const float* __restrict__ bh = half ? bdst : bsrc;
    __half* __restrict__ out = g_h[half];

    const int wid  = tid >> 5;
    const int lane = tid & 31;
    const int wm   = (wid >> 2) * 64;     // warp M offset 0/64
    const int wn   = (wid & 3) * 32;      // warp N offset 0/32/64/96
    const int row0 = blockIdx.x * 128;
    const int tg   = lane >> 2;
    const int tr   = lane & 3;

    float acc[4][4][4];
#pragma unroll
    for (int i = 0; i < 4; i++)
#pragma unroll
        for (int j = 0; j < 4; j++)
#pragma unroll
            for (int k = 0; k < 4; k++) acc[i][j][k] = 0.0f;

    const int lr = tid >> 1;              // row 0..127
    const int lc = (tid & 1) * 32;        // col half of the BK=64 chunk
    const bool rowok = (row0 + lr < N);
    const float* xrow = x + (size_t)(row0 + lr) * D + lc;
    const float* wrow = W + (size_t)lr * D + lc;

#pragma unroll
    for (int it = 0; it < 2; it++) {
        const int kt = it * 64;

        // Load + convert + store 32 floats per matrix per thread.
#pragma unroll
        for (int g = 0; g < 4; g++) {
            float4 u = make_float4(0.f,0.f,0.f,0.f), v = u;
            if (rowok) {
                u = *(const float4*)(xrow + kt + g * 8);
                v = *(const float4*)(xrow + kt + g * 8 + 4);
            }
            uint4 pk = make_uint4(h2u(__floats2half2_rn(u.x, u.y)),
                                  h2u(__floats2half2_rn(u.z, u.w)),
                                  h2u(__floats2half2_rn(v.x, v.y)),
                                  h2u(__floats2half2_rn(v.z, v.w)));
            *(uint4*)&As[lr][lc + g * 8] = pk;

            float4 a = *(const float4*)(wrow + kt + g * 8);
            float4 b = *(const float4*)(wrow + kt + g * 8 + 4);
            uint4 qk = make_uint4(h2u(__floats2half2_rn(a.x, a.y)),
                                  h2u(__floats2half2_rn(a.z, a.w)),
                                  h2u(__floats2half2_rn(b.x, b.y)),
                                  h2u(__floats2half2_rn(b.z, b.w)));
            *(uint4*)&Bs[lr][lc + g * 8] = qk;
        }
        __syncthreads();

#pragma unroll
        for (int kb = 0; kb < 64; kb += 16) {
            unsigned bf[4][2];
#pragma unroll
            for (int nt = 0; nt < 4; nt++) {
                const int jr = wn + nt * 8 + tg;
                bf[nt][0] = *(const unsigned*)&Bs[jr][kb + 2 * tr];
                bf[nt][1] = *(const unsigned*)&Bs[jr][kb + 2 * tr + 8];
            }
#pragma unroll
            for (int mt = 0; mt < 4; mt++) {
                const int ar = wm + mt * 16 + tg;
                unsigned a0 = *(const unsigned*)&As[ar    ][kb + 2 * tr];
                unsigned a1 = *(const unsigned*)&As[ar + 8][kb + 2 * tr];
                unsigned a2 = *(const unsigned*)&As[ar    ][kb + 2 * tr + 8];
                unsigned a3 = *(const unsigned*)&As[ar + 8][kb + 2 * tr + 8];
#pragma unroll
                for (int nt = 0; nt < 4; nt++)
                    mma_f16(acc[mt][nt], a0, a1, a2, a3, bf[nt][0], bf[nt][1]);
            }
        }
        __syncthreads();
    }

    // Epilogue: layout identical to the tf32 version.
#pragma unroll
    for (int mt = 0; mt < 4; mt++) {
#pragma unroll
        for (int nt = 0; nt < 4; nt++) {
            const int cg = wn + nt * 8 + 2 * tr;
            const float bb0 = bh[cg], bb1 = bh[cg + 1];
            const int r0g = row0 + wm + mt * 16 + tg;
            const int r1g = r0g + 8;
            if (r0g < N) {
                __half2 h = __floats2half2_rn(acc[mt][nt][0] + bb0,
                                              acc[mt][nt][1] + bb1);
                *(__half2*)(out + (size_t)r0g * D + cg) = h;
            }
            if (r1g < N) {
                __half2 h = __floats2half2_rn(acc[mt][nt][2] + bb0,
                                              acc[mt][nt][3] + bb1);
                *(__half2*)(out + (size_t)r1g * D + cg) = h;
            }
        }
    }
}

// ---------------------------------------------------------------------------
// Edge pass (unchanged from best): 16 lanes/edge, 2 edges/warp,
// evict_last gathers + evict_first streaming stores.
// ---------------------------------------------------------------------------
__global__ __launch_bounds__(256) void edge_kernel(
    const void* __restrict__ srcp, const void* __restrict__ dstp,
    const float* __restrict__ W_out, const float* __restrict__ b_out,
    float* __restrict__ score, float* __restrict__ embs,
    long long E, int N)
{
    __shared__ float4 ws[64];
    __shared__ float2 sc[16];

    const int tid = threadIdx.x;
    if (tid < 64) ws[tid] = ((const float4*)W_out)[tid];
    __syncthreads();

    unsigned long long pol_l, pol_s;
    asm("createpolicy.fractional.L2::evict_last.b64 %0, 1.0;"  : "=l"(pol_l));
    asm("createpolicy.fractional.L2::evict_first.b64 %0, 1.0;" : "=l"(pol_s));

    const int warp = tid >> 5;
    const int lane = tid & 31;
    const int sub  = lane >> 4;
    const int sl   = lane & 15;
    const long long e = (long long)blockIdx.x * 16 + warp * 2 + sub;

    const __half* __restrict__ hs = g_h[0];
    const __half* __restrict__ hd = g_h[1];

    if (e < E) {
        int s, d;
        if (g_idx64) {
            s = (int)((const long long*)srcp)[e];
            d = (int)((const long long*)dstp)[e];
        } else {
            s = ((const int*)srcp)[e];
            d = ((const int*)dstp)[e];
        }
        s = min(max(s, 0), N - 1);
        d = min(max(d, 0), N - 1);

        const __half* rs = hs + (size_t)s * D;
        const __half* rd = hd + (size_t)d * D;

        const uint2 sa_lo = ldg_el((const uint2*)rs + sl, pol_l);
        const uint2 sa_hi = ldg_el((const uint2*)(rs + 64) + sl, pol_l);
        const uint2 da_lo = ldg_el((const uint2*)rd + sl, pol_l);
        const uint2 da_hi = ldg_el((const uint2*)(rd + 64) + sl, pol_l);

        const __half2 z = __float2half2_rn(0.0f);
        __half2 l0 = __hmax2(__hadd2(*(const __half2*)&sa_lo.x, *(const __half2*)&da_lo.x), z);
        __half2 l1 = __hmax2(__hadd2(*(const __half2*)&sa_lo.y, *(const __half2*)&da_lo.y), z);
        __half2 h0 = __hmax2(__hadd2(*(const __half2*)&sa_hi.x, *(const __half2*)&da_hi.x), z);
        __half2 h1 = __hmax2(__hadd2(*(const __half2*)&sa_hi.y, *(const __half2*)&da_hi.y), z);

        float2 fl0 = __half22float2(l0);
        float2 fl1 = __half22float2(l1);
        float2 fh0 = __half22float2(h0);
        float2 fh1 = __half22float2(h1);

        float* ep = embs + (size_t)e * D;
        stg_ef(ep + sl * 4,      make_float4(fl0.x, fl0.y, fl1.x, fl1.y), pol_s);
        stg_ef(ep + 64 + sl * 4, make_float4(fh0.x, fh0.y, fh1.x, fh1.y), pol_s);

        const float4 wa_lo = ws[sl];
        const float4 wa_hi = ws[16 + sl];
        const float4 wb_lo = ws[32 + sl];
        const float4 wb_hi = ws[48 + sl];

        float d0 = fl0.x*wa_lo.x + fl0.y*wa_lo.y + fl1.x*wa_lo.z + fl1.y*wa_lo.w
                 + fh0.x*wa_hi.x + fh0.y*wa_hi.y + fh1.x*wa_hi.z + fh1.y*wa_hi.w;
        float d1 = fl0.x*wb_lo.x + fl0.y*wb_lo.y + fl1.x*wb_lo.z + fl1.y*wb_lo.w
                 + fh0.x*wb_hi.x + fh0.y*wb_hi.y + fh1.x*wb_hi.z + fh1.y*wb_hi.w;

#pragma unroll
        for (int o = 8; o > 0; o >>= 1) {
            d0 += __shfl_xor_sync(0xffffffffu, d0, o);
            d1 += __shfl_xor_sync(0xffffffffu, d1, o);
        }
        if (sl == 0)
            sc[warp * 2 + sub] = make_float2(d0 + b_out[0], d1 + b_out[1]);
    }
    __syncthreads();

    const long long base = (long long)blockIdx.x * 16;
    if (tid < 16 && base + tid < E)
        ((float2*)score)[base + tid] = sc[tid];
}

extern "C" void kernel_launch(void* const* d_in, const int* in_sizes, int n_in,
                              void* d_out, int out_size)
{
    const float* x     = (const float*)d_in[0];
    const void*  src   = d_in[1];
    const void*  dst   = d_in[2];
    const float* W_src = (const float*)d_in[3];
    const float* b_src = (const float*)d_in[4];
    const float* W_dst = (const float*)d_in[5];
    const float* b_dst = (const float*)d_in[6];
    const float* W_out = (const float*)d_in[7];
    const float* b_out = (const float*)d_in[8];

    const int N = in_sizes[0] / D;
    const long long E = in_sizes[1];

    float* out   = (float*)d_out;
    float* score = out;                       // [E, 2]
    float* embs  = out + (size_t)E * 2;       // [E, 128]

    dim3 gg((N + 127) / 128, 2);
    node_gemm_half<<<gg, 256>>>(x, W_src, b_src, W_dst, b_dst,
                                (const long long*)src, N);

    const int eb = (int)((E + 15) / 16);
    edge_kernel<<<eb, 256>>>(src, dst, W_out, b_out, score, embs, E, N);
}

// round 13
// speedup vs baseline: 1.0666x; 1.0666x over previous
#include <cuda_runtime.h>
#include <cuda_fp16.h>

#define D 128
#define NMAX 100000
#define PAD 20

__device__ __half g_h[2][(size_t)NMAX * D];
__device__ int g_idx64;

__device__ __forceinline__ unsigned f2tf32(float f) {
    unsigned u;
    asm("cvt.rna.tf32.f32 %0, %1;" : "=r"(u) : "f"(f));
    return u;
}

__device__ __forceinline__ void mma_tf32(float c[4], unsigned a0, unsigned a1,
                                         unsigned a2, unsigned a3,
                                         unsigned b0, unsigned b1) {
    asm volatile(
        "mma.sync.aligned.m16n8k8.row.col.f32.tf32.tf32.f32 "
        "{%0,%1,%2,%3},{%4,%5,%6,%7},{%8,%9},{%0,%1,%2,%3};"
        : "+f"(c[0]), "+f"(c[1]), "+f"(c[2]), "+f"(c[3])
        : "r"(a0), "r"(a1), "r"(a2), "r"(a3), "r"(b0), "r"(b1));
}

__device__ __forceinline__ uint2 ldg_el(const void* p, unsigned long long pol) {
    uint2 r;
    asm volatile("ld.global.nc.L2::cache_hint.v2.u32 {%0,%1}, [%2], %3;"
                 : "=r"(r.x), "=r"(r.y) : "l"(p), "l"(pol));
    return r;
}

__device__ __forceinline__ void stg_ef(void* p, float4 v, unsigned long long pol) {
    asm volatile("st.global.L2::cache_hint.v4.f32 [%0], {%1,%2,%3,%4}, %5;"
                 :: "l"(p), "f"(v.x), "f"(v.y), "f"(v.z), "f"(v.w), "l"(pol)
                 : "memory");
}

// ---------------------------------------------------------------------------
// Node GEMM (round-11 measured-best): tf32 mma, one half per blockIdx.y,
// 256 threads, register-pipelined K loop, 2 blocks/SM.
// ---------------------------------------------------------------------------
__global__ __launch_bounds__(256, 2) void node_gemm_half(
    const float* __restrict__ x,
    const float* __restrict__ Wsrc, const float* __restrict__ bsrc,
    const float* __restrict__ Wdst, const float* __restrict__ bdst,
    const long long* __restrict__ idxprobe, int N)
{
    __shared__ unsigned As[128][PAD];
    __shared__ unsigned Bs[128][PAD];

    const int tid  = threadIdx.x;
    const int half = blockIdx.y;

    if (blockIdx.x == 0 && half == 0 && tid == 0) {
        int ok = 0;
#pragma unroll
        for (int i = 0; i < 16; i++) {
            long long v = idxprobe[i];
            if (v >= 0 && v < (long long)N) ok++;
        }
        g_idx64 = (ok >= 12) ? 1 : 0;
    }

    const float* __restrict__ W  = half ? Wdst : Wsrc;
    const float* __restrict__ bh = half ? bdst : bsrc;
    __half* __restrict__ out = g_h[half];

    const int wid  = tid >> 5;
    const int lane = tid & 31;
    const int wm   = (wid >> 2) * 64;
    const int wn   = (wid & 3) * 32;
    const int row0 = blockIdx.x * 128;
    const int tg   = lane >> 2;
    const int tr   = lane & 3;

    float acc[4][4][4];
#pragma unroll
    for (int i = 0; i < 4; i++)
#pragma unroll
        for (int j = 0; j < 4; j++)
#pragma unroll
            for (int k = 0; k < 4; k++) acc[i][j][k] = 0.0f;

    const int lrow = tid >> 1;
    const int lcol = (tid & 1) * 8;
    const bool rowok = (row0 + lrow < N);
    const float* xrow = x + (size_t)(row0 + lrow) * D + lcol;
    const float* wr   = W + (size_t)lrow * D + lcol;

    float4 a0v = make_float4(0.f,0.f,0.f,0.f), a1v = a0v;
    if (rowok) { a0v = *(const float4*)xrow; a1v = *(const float4*)(xrow + 4); }
    float4 w0v = *(const float4*)wr;
    float4 w1v = *(const float4*)(wr + 4);

#pragma unroll
    for (int it = 0; it < 8; it++) {
        As[lrow][lcol+0] = f2tf32(a0v.x); As[lrow][lcol+1] = f2tf32(a0v.y);
        As[lrow][lcol+2] = f2tf32(a0v.z); As[lrow][lcol+3] = f2tf32(a0v.w);
        As[lrow][lcol+4] = f2tf32(a1v.x); As[lrow][lcol+5] = f2tf32(a1v.y);
        As[lrow][lcol+6] = f2tf32(a1v.z); As[lrow][lcol+7] = f2tf32(a1v.w);
        Bs[lrow][lcol+0] = f2tf32(w0v.x); Bs[lrow][lcol+1] = f2tf32(w0v.y);
        Bs[lrow][lcol+2] = f2tf32(w0v.z); Bs[lrow][lcol+3] = f2tf32(w0v.w);
        Bs[lrow][lcol+4] = f2tf32(w1v.x); Bs[lrow][lcol+5] = f2tf32(w1v.y);
        Bs[lrow][lcol+6] = f2tf32(w1v.z); Bs[lrow][lcol+7] = f2tf32(w1v.w);
        __syncthreads();

        if (it < 7) {
            const int off = (it + 1) * 16;
            a0v = make_float4(0.f,0.f,0.f,0.f); a1v = a0v;
            if (rowok) {
                a0v = *(const float4*)(xrow + off);
                a1v = *(const float4*)(xrow + off + 4);
            }
            w0v = *(const float4*)(wr + off);
            w1v = *(const float4*)(wr + off + 4);
        }

#pragma unroll
        for (int kk = 0; kk < 16; kk += 8) {
            unsigned bf[4][2];
#pragma unroll
            for (int nt = 0; nt < 4; nt++) {
                bf[nt][0] = Bs[wn + nt*8 + tg][kk + tr];
                bf[nt][1] = Bs[wn + nt*8 + tg][kk + tr + 4];
            }
#pragma unroll
            for (int mt = 0; mt < 4; mt++) {
                const int ar = wm + mt*16 + tg;
                unsigned q0 = As[ar    ][kk + tr];
                unsigned q1 = As[ar + 8][kk + tr];
                unsigned q2 = As[ar    ][kk + tr + 4];
                unsigned q3 = As[ar + 8][kk + tr + 4];
#pragma unroll
                for (int nt = 0; nt < 4; nt++)
                    mma_tf32(acc[mt][nt], q0, q1, q2, q3, bf[nt][0], bf[nt][1]);
            }
        }
        __syncthreads();
    }

#pragma unroll
    for (int mt = 0; mt < 4; mt++) {
#pragma unroll
        for (int nt = 0; nt < 4; nt++) {
            const int cg = wn + nt*8 + 2*tr;
            const float bb0 = bh[cg], bb1 = bh[cg + 1];
            const int r0g = row0 + wm + mt*16 + tg;
            const int r1g = r0g + 8;
            if (r0g < N) {
                __half2 h = __floats2half2_rn(acc[mt][nt][0] + bb0,
                                              acc[mt][nt][1] + bb1);
                *(__half2*)(out + (size_t)r0g * D + cg) = h;
            }
            if (r1g < N) {
                __half2 h = __floats2half2_rn(acc[mt][nt][2] + bb0,
                                              acc[mt][nt][3] + bb1);
                *(__half2*)(out + (size_t)r1g * D + cg) = h;
            }
        }
    }
}

// ---------------------------------------------------------------------------
// Edge pass: grid-stride persistent, 16 lanes/edge, 2 edges/warp/iter.
// Index prefetch one iteration ahead breaks the index->gather dependency
// chain. No __syncthreads (W_out via __ldg, scores stored directly).
// ---------------------------------------------------------------------------
__global__ __launch_bounds__(256) void edge_kernel(
    const void* __restrict__ srcp, const void* __restrict__ dstp,
    const float* __restrict__ W_out, const float* __restrict__ b_out,
    float* __restrict__ score, float* __restrict__ embs,
    long long E, int N)
{
    const int tid  = threadIdx.x;
    const int warp = tid >> 5;
    const int lane = tid & 31;
    const int sub  = lane >> 4;
    const int sl   = lane & 15;

    unsigned long long pol_l, pol_s;
    asm("createpolicy.fractional.L2::evict_last.b64 %0, 1.0;"  : "=l"(pol_l));
    asm("createpolicy.fractional.L2::evict_first.b64 %0, 1.0;" : "=l"(pol_s));

    // W_out fragments (read-only, L1-resident after first touch).
    const float4* W4 = (const float4*)W_out;
    const float4 wa_lo = __ldg(W4 + sl);
    const float4 wa_hi = __ldg(W4 + 16 + sl);
    const float4 wb_lo = __ldg(W4 + 32 + sl);
    const float4 wb_hi = __ldg(W4 + 48 + sl);
    const float  bo0   = __ldg(b_out);
    const float  bo1   = __ldg(b_out + 1);

    const __half* __restrict__ hs = g_h[0];
    const __half* __restrict__ hd = g_h[1];
    const bool i64 = (g_idx64 != 0);

    const long long stride = (long long)gridDim.x * 16;
    long long e = (long long)blockIdx.x * 16 + warp * 2 + sub;

    // Prefetch indices for the first iteration.
    int s_n = 0, d_n = 0;
    if (e < E) {
        if (i64) {
            s_n = (int)((const long long*)srcp)[e];
            d_n = (int)((const long long*)dstp)[e];
        } else {
            s_n = ((const int*)srcp)[e];
            d_n = ((const int*)dstp)[e];
        }
    }

    const __half2 z = __float2half2_rn(0.0f);

    while (e < E) {
        const int s = min(max(s_n, 0), N - 1);
        const int d = min(max(d_n, 0), N - 1);
        const long long en = e + stride;

        // Issue gathers for this iteration (addresses ready via prefetch).
        const __half* rs = hs + (size_t)s * D;
        const __half* rd = hd + (size_t)d * D;
        const uint2 sa_lo = ldg_el((const uint2*)rs + sl, pol_l);
        const uint2 sa_hi = ldg_el((const uint2*)(rs + 64) + sl, pol_l);
        const uint2 da_lo = ldg_el((const uint2*)rd + sl, pol_l);
        const uint2 da_hi = ldg_el((const uint2*)(rd + 64) + sl, pol_l);

        // Prefetch next iteration's indices while gathers are in flight.
        if (en < E) {
            if (i64) {
                s_n = (int)((const long long*)srcp)[en];
                d_n = (int)((const long long*)dstp)[en];
            } else {
                s_n = ((const int*)srcp)[en];
                d_n = ((const int*)dstp)[en];
            }
        }

        __half2 l0 = __hmax2(__hadd2(*(const __half2*)&sa_lo.x, *(const __half2*)&da_lo.x), z);
        __half2 l1 = __hmax2(__hadd2(*(const __half2*)&sa_lo.y, *(const __half2*)&da_lo.y), z);
        __half2 h0 = __hmax2(__hadd2(*(const __half2*)&sa_hi.x, *(const __half2*)&da_hi.x), z);
        __half2 h1 = __hmax2(__hadd2(*(const __half2*)&sa_hi.y, *(const __half2*)&da_hi.y), z);

        float2 fl0 = __half22float2(l0);
        float2 fl1 = __half22float2(l1);
        float2 fh0 = __half22float2(h0);
        float2 fh1 = __half22float2(h1);

        float* ep = embs + (size_t)e * D;
        stg_ef(ep + sl * 4,      make_float4(fl0.x, fl0.y, fl1.x, fl1.y), pol_s);
        stg_ef(ep + 64 + sl * 4, make_float4(fh0.x, fh0.y, fh1.x, fh1.y), pol_s);

        float d0 = fl0.x*wa_lo.x + fl0.y*wa_lo.y + fl1.x*wa_lo.z + fl1.y*wa_lo.w
                 + fh0.x*wa_hi.x + fh0.y*wa_hi.y + fh1.x*wa_hi.z + fh1.y*wa_hi.w;
        float d1 = fl0.x*wb_lo.x + fl0.y*wb_lo.y + fl1.x*wb_lo.z + fl1.y*wb_lo.w
                 + fh0.x*wb_hi.x + fh0.y*wb_hi.y + fh1.x*wb_hi.z + fh1.y*wb_hi.w;

#pragma unroll
        for (int o = 8; o > 0; o >>= 1) {
            d0 += __shfl_xor_sync(0xffffffffu, d0, o);
            d1 += __shfl_xor_sync(0xffffffffu, d1, o);
        }
        if (sl == 0)
            ((float2*)score)[e] = make_float2(d0 + bo0, d1 + bo1);

        e = en;
    }
}

extern "C" void kernel_launch(void* const* d_in, const int* in_sizes, int n_in,
                              void* d_out, int out_size)
{
    const float* x     = (const float*)d_in[0];
    const void*  src   = d_in[1];
    const void*  dst   = d_in[2];
    const float* W_src = (const float*)d_in[3];
    const float* b_src = (const float*)d_in[4];
    const float* W_dst = (const float*)d_in[5];
    const float* b_dst = (const float*)d_in[6];
    const float* W_out = (const float*)d_in[7];
    const float* b_out = (const float*)d_in[8];

    const int N = in_sizes[0] / D;
    const long long E = in_sizes[1];

    float* out   = (float*)d_out;
    float* score = out;                       // [E, 2]
    float* embs  = out + (size_t)E * 2;       // [E, 128]

    dim3 gg((N + 127) / 128, 2);
    node_gemm_half<<<gg, 256>>>(x, W_src, b_src, W_dst, b_dst,
                                (const long long*)src, N);

    // Persistent grid: ~8 blocks/SM resident; grid-stride covers all edges.
    const int eb = 148 * 8;
    edge_kernel<<<eb, 256>>>(src, dst, W_out, b_out, score, embs, E, N);
}

// round 14
// speedup vs baseline: 1.1161x; 1.0465x over previous
#include <cuda_runtime.h>
#include <cuda_fp16.h>

#define D 128
#define NMAX 100000
#define PAD 20

__device__ __half g_h[2][(size_t)NMAX * D];
__device__ int g_idx64;

__device__ __forceinline__ unsigned f2tf32(float f) {
    unsigned u;
    asm("cvt.rna.tf32.f32 %0, %1;" : "=r"(u) : "f"(f));
    return u;
}

__device__ __forceinline__ void mma_tf32(float c[4], unsigned a0, unsigned a1,
                                         unsigned a2, unsigned a3,
                                         unsigned b0, unsigned b1) {
    asm volatile(
        "mma.sync.aligned.m16n8k8.row.col.f32.tf32.tf32.f32 "
        "{%0,%1,%2,%3},{%4,%5,%6,%7},{%8,%9},{%0,%1,%2,%3};"
        : "+f"(c[0]), "+f"(c[1]), "+f"(c[2]), "+f"(c[3])
        : "r"(a0), "r"(a1), "r"(a2), "r"(a3), "r"(b0), "r"(b1));
}

__device__ __forceinline__ uint2 ldg_el(const void* p, unsigned long long pol) {
    uint2 r;
    asm volatile("ld.global.nc.L2::cache_hint.v2.u32 {%0,%1}, [%2], %3;"
                 : "=r"(r.x), "=r"(r.y) : "l"(p), "l"(pol));
    return r;
}

__device__ __forceinline__ void stg_ef(void* p, float4 v, unsigned long long pol) {
    asm volatile("st.global.L2::cache_hint.v4.f32 [%0], {%1,%2,%3,%4}, %5;"
                 :: "l"(p), "f"(v.x), "f"(v.y), "f"(v.z), "f"(v.w), "l"(pol)
                 : "memory");
}

// ---------------------------------------------------------------------------
// Node GEMM (measured-best): tf32 mma, one half per blockIdx.y, 256 threads,
// register-pipelined K loop, 2 blocks/SM.
// ---------------------------------------------------------------------------
__global__ __launch_bounds__(256, 2) void node_gemm_half(
    const float* __restrict__ x,
    const float* __restrict__ Wsrc, const float* __restrict__ bsrc,
    const float* __restrict__ Wdst, const float* __restrict__ bdst,
    const long long* __restrict__ idxprobe, int N)
{
    __shared__ unsigned As[128][PAD];
    __shared__ unsigned Bs[128][PAD];

    const int tid  = threadIdx.x;
    const int half = blockIdx.y;

    if (blockIdx.x == 0 && half == 0 && tid == 0) {
        int ok = 0;
#pragma unroll
        for (int i = 0; i < 16; i++) {
            long long v = idxprobe[i];
            if (v >= 0 && v < (long long)N) ok++;
        }
        g_idx64 = (ok >= 12) ? 1 : 0;
    }

    const float* __restrict__ W  = half ? Wdst : Wsrc;
    const float* __restrict__ bh = half ? bdst : bsrc;
    __half* __restrict__ out = g_h[half];

    const int wid  = tid >> 5;
    const int lane = tid & 31;
    const int wm   = (wid >> 2) * 64;
    const int wn   = (wid & 3) * 32;
    const int row0 = blockIdx.x * 128;
    const int tg   = lane >> 2;
    const int tr   = lane & 3;

    float acc[4][4][4];
#pragma unroll
    for (int i = 0; i < 4; i++)
#pragma unroll
        for (int j = 0; j < 4; j++)
#pragma unroll
            for (int k = 0; k < 4; k++) acc[i][j][k] = 0.0f;

    const int lrow = tid >> 1;
    const int lcol = (tid & 1) * 8;
    const bool rowok = (row0 + lrow < N);
    const float* xrow = x + (size_t)(row0 + lrow) * D + lcol;
    const float* wr   = W + (size_t)lrow * D + lcol;

    float4 a0v = make_float4(0.f,0.f,0.f,0.f), a1v = a0v;
    if (rowok) { a0v = *(const float4*)xrow; a1v = *(const float4*)(xrow + 4); }
    float4 w0v = *(const float4*)wr;
    float4 w1v = *(const float4*)(wr + 4);

#pragma unroll
    for (int it = 0; it < 8; it++) {
        As[lrow][lcol+0] = f2tf32(a0v.x); As[lrow][lcol+1] = f2tf32(a0v.y);
        As[lrow][lcol+2] = f2tf32(a0v.z); As[lrow][lcol+3] = f2tf32(a0v.w);
        As[lrow][lcol+4] = f2tf32(a1v.x); As[lrow][lcol+5] = f2tf32(a1v.y);
        As[lrow][lcol+6] = f2tf32(a1v.z); As[lrow][lcol+7] = f2tf32(a1v.w);
        Bs[lrow][lcol+0] = f2tf32(w0v.x); Bs[lrow][lcol+1] = f2tf32(w0v.y);
        Bs[lrow][lcol+2] = f2tf32(w0v.z); Bs[lrow][lcol+3] = f2tf32(w0v.w);
        Bs[lrow][lcol+4] = f2tf32(w1v.x); Bs[lrow][lcol+5] = f2tf32(w1v.y);
        Bs[lrow][lcol+6] = f2tf32(w1v.z); Bs[lrow][lcol+7] = f2tf32(w1v.w);
        __syncthreads();

        if (it < 7) {
            const int off = (it + 1) * 16;
            a0v = make_float4(0.f,0.f,0.f,0.f); a1v = a0v;
            if (rowok) {
                a0v = *(const float4*)(xrow + off);
                a1v = *(const float4*)(xrow + off + 4);
            }
            w0v = *(const float4*)(wr + off);
            w1v = *(const float4*)(wr + off + 4);
        }

#pragma unroll
        for (int kk = 0; kk < 16; kk += 8) {
            unsigned bf[4][2];
#pragma unroll
            for (int nt = 0; nt < 4; nt++) {
                bf[nt][0] = Bs[wn + nt*8 + tg][kk + tr];
                bf[nt][1] = Bs[wn + nt*8 + tg][kk + tr + 4];
            }
#pragma unroll
            for (int mt = 0; mt < 4; mt++) {
                const int ar = wm + mt*16 + tg;
                unsigned q0 = As[ar    ][kk + tr];
                unsigned q1 = As[ar + 8][kk + tr];
                unsigned q2 = As[ar    ][kk + tr + 4];
                unsigned q3 = As[ar + 8][kk + tr + 4];
#pragma unroll
                for (int nt = 0; nt < 4; nt++)
                    mma_tf32(acc[mt][nt], q0, q1, q2, q3, bf[nt][0], bf[nt][1]);
            }
        }
        __syncthreads();
    }

#pragma unroll
    for (int mt = 0; mt < 4; mt++) {
#pragma unroll
        for (int nt = 0; nt < 4; nt++) {
            const int cg = wn + nt*8 + 2*tr;
            const float bb0 = bh[cg], bb1 = bh[cg + 1];
            const int r0g = row0 + wm + mt*16 + tg;
            const int r1g = r0g + 8;
            if (r0g < N) {
                __half2 h = __floats2half2_rn(acc[mt][nt][0] + bb0,
                                              acc[mt][nt][1] + bb1);
                *(__half2*)(out + (size_t)r0g * D + cg) = h;
            }
            if (r1g < N) {
                __half2 h = __floats2half2_rn(acc[mt][nt][2] + bb0,
                                              acc[mt][nt][3] + bb1);
                *(__half2*)(out + (size_t)r1g * D + cg) = h;
            }
        }
    }
}

// ---------------------------------------------------------------------------
// Edge pass: grid-stride persistent (exactly one resident wave), 16
// lanes/edge, index prefetch one iteration ahead, no __syncthreads.
// launch_bounds(256,6): regs <= 42 -> 6 blocks/SM -> 48 warps (75% occ).
// ---------------------------------------------------------------------------
__global__ __launch_bounds__(256, 6) void edge_kernel(
    const void* __restrict__ srcp, const void* __restrict__ dstp,
    const float* __restrict__ W_out, const float* __restrict__ b_out,
    float* __restrict__ score, float* __restrict__ embs,
    long long E, int N)
{
    const int tid  = threadIdx.x;
    const int warp = tid >> 5;
    const int lane = tid & 31;
    const int sub  = lane >> 4;
    const int sl   = lane & 15;

    unsigned long long pol_l, pol_s;
    asm("createpolicy.fractional.L2::evict_last.b64 %0, 1.0;"  : "=l"(pol_l));
    asm("createpolicy.fractional.L2::evict_first.b64 %0, 1.0;" : "=l"(pol_s));

    const float4* W4 = (const float4*)W_out;
    const float4 wa_lo = __ldg(W4 + sl);
    const float4 wa_hi = __ldg(W4 + 16 + sl);
    const float4 wb_lo = __ldg(W4 + 32 + sl);
    const float4 wb_hi = __ldg(W4 + 48 + sl);
    const float  bo0   = __ldg(b_out);
    const float  bo1   = __ldg(b_out + 1);

    const __half* __restrict__ hs = g_h[0];
    const __half* __restrict__ hd = g_h[1];
    const bool i64 = (g_idx64 != 0);

    const long long stride = (long long)gridDim.x * 16;
    long long e = (long long)blockIdx.x * 16 + warp * 2 + sub;

    int s_n = 0, d_n = 0;
    if (e < E) {
        if (i64) {
            s_n = (int)((const long long*)srcp)[e];
            d_n = (int)((const long long*)dstp)[e];
        } else {
            s_n = ((const int*)srcp)[e];
            d_n = ((const int*)dstp)[e];
        }
    }

    const __half2 z = __float2half2_rn(0.0f);

    while (e < E) {
        const int s = min(max(s_n, 0), N - 1);
        const int d = min(max(d_n, 0), N - 1);
        const long long en = e + stride;

        const __half* rs = hs + (size_t)s * D;
        const __half* rd = hd + (size_t)d * D;
        const uint2 sa_lo = ldg_el((const uint2*)rs + sl, pol_l);
        const uint2 sa_hi = ldg_el((const uint2*)(rs + 64) + sl, pol_l);
        const uint2 da_lo = ldg_el((const uint2*)rd + sl, pol_l);
        const uint2 da_hi = ldg_el((const uint2*)(rd + 64) + sl, pol_l);

        if (en < E) {
            if (i64) {
                s_n = (int)((const long long*)srcp)[en];
                d_n = (int)((const long long*)dstp)[en];
            } else {
                s_n = ((const int*)srcp)[en];
                d_n = ((const int*)dstp)[en];
            }
        }

        __half2 l0 = __hmax2(__hadd2(*(const __half2*)&sa_lo.x, *(const __half2*)&da_lo.x), z);
        __half2 l1 = __hmax2(__hadd2(*(const __half2*)&sa_lo.y, *(const __half2*)&da_lo.y), z);
        __half2 h0 = __hmax2(__hadd2(*(const __half2*)&sa_hi.x, *(const __half2*)&da_hi.x), z);
        __half2 h1 = __hmax2(__hadd2(*(const __half2*)&sa_hi.y, *(const __half2*)&da_hi.y), z);

        float2 fl0 = __half22float2(l0);
        float2 fl1 = __half22float2(l1);
        float2 fh0 = __half22float2(h0);
        float2 fh1 = __half22float2(h1);

        float* ep = embs + (size_t)e * D;
        stg_ef(ep + sl * 4,      make_float4(fl0.x, fl0.y, fl1.x, fl1.y), pol_s);
        stg_ef(ep + 64 + sl * 4, make_float4(fh0.x, fh0.y, fh1.x, fh1.y), pol_s);

        float d0 = fl0.x*wa_lo.x + fl0.y*wa_lo.y + fl1.x*wa_lo.z + fl1.y*wa_lo.w
                 + fh0.x*wa_hi.x + fh0.y*wa_hi.y + fh1.x*wa_hi.z + fh1.y*wa_hi.w;
        float d1 = fl0.x*wb_lo.x + fl0.y*wb_lo.y + fl1.x*wb_lo.z + fl1.y*wb_lo.w
                 + fh0.x*wb_hi.x + fh0.y*wb_hi.y + fh1.x*wb_hi.z + fh1.y*wb_hi.w;

#pragma unroll
        for (int o = 8; o > 0; o >>= 1) {
            d0 += __shfl_xor_sync(0xffffffffu, d0, o);
            d1 += __shfl_xor_sync(0xffffffffu, d1, o);
        }
        if (sl == 0)
            ((float2*)score)[e] = make_float2(d0 + bo0, d1 + bo1);

        e = en;
    }
}

extern "C" void kernel_launch(void* const* d_in, const int* in_sizes, int n_in,
                              void* d_out, int out_size)
{
    const float* x     = (const float*)d_in[0];
    const void*  src   = d_in[1];
    const void*  dst   = d_in[2];
    const float* W_src = (const float*)d_in[3];
    const float* b_src = (const float*)d_in[4];
    const float* W_dst = (const float*)d_in[5];
    const float* b_dst = (const float*)d_in[6];
    const float* W_out = (const float*)d_in[7];
    const float* b_out = (const float*)d_in[8];

    const int N = in_sizes[0] / D;
    const long long E = in_sizes[1];

    float* out   = (float*)d_out;
    float* score = out;                       // [E, 2]
    float* embs  = out + (size_t)E * 2;       // [E, 128]

    dim3 gg((N + 127) / 128, 2);
    node_gemm_half<<<gg, 256>>>(x, W_src, b_src, W_dst, b_dst,
                                (const long long*)src, N);

    // Exactly one resident wave: 6 blocks/SM x 148 SMs.
    const int eb = 148 * 6;
    edge_kernel<<<eb, 256>>>(src, dst, W_out, b_out, score, embs, E, N);
}